// round 10
// baseline (speedup 1.0000x reference)
#include <cuda_runtime.h>
#include <cuda_bf16.h>
#include <cuda_fp16.h>
#include <cstdint>

// Problem constants
#define Bq 2
#define Tq 512
#define Sq 2048
#define Hq 768
#define Lq 32
#define NHq 12
#define HD 64
#define IM 3072
#define NSPAN (Bq*Sq)          // 4096
#define NTOK  (Bq*Tq)          // 1024

typedef __nv_bfloat16 bf16;

// -------------------- device scratch --------------------
__device__ float g_q[Hq];
__device__ float g_KV[(size_t)NTOK * 2 * Hq];
__device__ __half g_V16[(size_t)NTOK * Hq];
__device__ float g_tokscore[(size_t)NTOK * NHq];
__device__ bf16  g_tokpe_h[(size_t)NTOK * Hq], g_tokpe_l[(size_t)NTOK * Hq];
__device__ bf16  g_wkv_h[(size_t)2 * Hq * Hq], g_wkv_l[(size_t)2 * Hq * Hq];
__device__ __half g_wout_f16[(size_t)Hq * Hq];
__device__ __half g_w1_f16[(size_t)IM * Hq];
__device__ __half g_w2_f16[(size_t)Hq * IM];
__device__ __half g_ctx_f16[(size_t)NSPAN * Hq];
__device__ float g_pre1[(size_t)NSPAN * Hq];
__device__ float g_x1[(size_t)NSPAN * Hq];
__device__ __half g_x1_f16[(size_t)NSPAN * Hq];
__device__ __half g_h1_f16[(size_t)NSPAN * IM];
__device__ float g_pre2[(size_t)NSPAN * Hq];
__device__ unsigned char g_mask[NSPAN];

// -------------------- helpers --------------------
__device__ __forceinline__ uint32_t smem_u32(const void* p) {
    uint32_t a;
    asm("{ .reg .u64 t; cvta.to.shared.u64 t, %1; cvt.u32.u64 %0, t; }" : "=r"(a) : "l"(p));
    return a;
}
#define SW128(o) ((o) ^ (((o) >> 3) & 0x70))

__device__ __forceinline__ void ldm_x4(uint32_t& r0, uint32_t& r1, uint32_t& r2, uint32_t& r3,
                                       uint32_t addr) {
    asm volatile("ldmatrix.sync.aligned.m8n8.x4.shared.b16 {%0,%1,%2,%3}, [%4];"
                 : "=r"(r0), "=r"(r1), "=r"(r2), "=r"(r3) : "r"(addr));
}
__device__ __forceinline__ void mma16816(float* d, const uint32_t* a, const uint32_t* b) {
    asm volatile(
        "mma.sync.aligned.m16n8k16.row.col.f32.bf16.bf16.f32 "
        "{%0,%1,%2,%3}, {%4,%5,%6,%7}, {%8,%9}, {%0,%1,%2,%3};"
        : "+f"(d[0]), "+f"(d[1]), "+f"(d[2]), "+f"(d[3])
        : "r"(a[0]), "r"(a[1]), "r"(a[2]), "r"(a[3]), "r"(b[0]), "r"(b[1]));
}
__device__ __forceinline__ void mma16816h(float* d, const uint32_t* a, const uint32_t* b) {
    asm volatile(
        "mma.sync.aligned.m16n8k16.row.col.f32.f16.f16.f32 "
        "{%0,%1,%2,%3}, {%4,%5,%6,%7}, {%8,%9}, {%0,%1,%2,%3};"
        : "+f"(d[0]), "+f"(d[1]), "+f"(d[2]), "+f"(d[3])
        : "r"(a[0]), "r"(a[1]), "r"(a[2]), "r"(a[3]), "r"(b[0]), "r"(b[1]));
}
__device__ __forceinline__ void cp16(uint32_t dst, const void* src) {
    asm volatile("cp.async.cg.shared.global [%0], [%1], 16;" :: "r"(dst), "l"(src));
}
#define CP_COMMIT() asm volatile("cp.async.commit_group;" ::: "memory")
template<int N> __device__ __forceinline__ void cp_wait() {
    asm volatile("cp.async.wait_group %0;" :: "n"(N) : "memory");
}

// -------------------- mask dtype sniffing + conversion --------------------
__global__ void mask_conv_k(const void* __restrict__ raw) {
    __shared__ int notInt, notFloat;
    const int t = threadIdx.x;
    if (t == 0) { notInt = 0; notFloat = 0; }
    __syncthreads();
    {
        const unsigned int v = ((const unsigned int*)raw)[t];
        if (v != 0u && v != 1u) notInt = 1;
        if (v != 0u && v != 0x3F800000u) notFloat = 1;
    }
    __syncthreads();
    const int mode = (!notInt) ? 0 : ((!notFloat) ? 1 : 2);
    for (int i = t; i < NSPAN; i += 256) {
        unsigned char m;
        if (mode == 0)      m = (((const int*)raw)[i] != 0);
        else if (mode == 1) m = (((const float*)raw)[i] != 0.f);
        else                m = (((const unsigned char*)raw)[i] != 0);
        g_mask[i] = m;
    }
}

// -------------------- q projection --------------------
__global__ void compute_q_k(const float* __restrict__ dq,
                            const float* __restrict__ W,
                            const float* __restrict__ b) {
    int i = blockIdx.x * blockDim.x + threadIdx.x;
    if (i < Hq) {
        float s = b[i];
        const float* w = W + (size_t)i * Hq;
        #pragma unroll 8
        for (int h = 0; h < Hq; h++) s = fmaf(dq[h], w[h], s);
        g_q[i] = s;
    }
}

// -------------------- per-token attention scores --------------------
__global__ __launch_bounds__(256)
void score_k() {
    const int wid = threadIdx.x >> 5, lane = threadIdx.x & 31;
    const int t = blockIdx.x * 8 + wid;
    const float* Krow = g_KV + (size_t)t * (2 * Hq);
    #pragma unroll
    for (int n = 0; n < NHq; n++) {
        const int d = n * HD + lane * 2;
        float2 kk = *(const float2*)(Krow + d);
        float2 qq = *(const float2*)(g_q + d);
        float a = kk.x * qq.x + kk.y * qq.y;
        #pragma unroll
        for (int o = 16; o > 0; o >>= 1) a += __shfl_xor_sync(0xffffffffu, a, o);
        if (lane == 0) g_tokscore[t * NHq + n] = a * 0.125f;
    }
}

// -------------------- fused operand prep (grid-stride over 5 regions) --------------------
#define PN0 (NTOK * Hq / 4)                 // tokpe split
#define PN1 (PN0 + 2 * Hq * Hq / 4)         // wkv split
#define PN2 (PN1 + Hq * Hq / 4)             // wout cvt
#define PN3 (PN2 + IM * Hq / 4)             // w1 cvt
#define PN4 (PN3 + Hq * IM / 4)             // w2 cvt

__global__ __launch_bounds__(256)
void prep_k(const float* __restrict__ tok, const float* __restrict__ pe,
            const float* __restrict__ in_proj_w, const float* __restrict__ out_proj_w,
            const float* __restrict__ ffn_w1, const float* __restrict__ ffn_w2) {
    const int i = blockIdx.x * 256 + threadIdx.x;
    if (i >= PN4) return;
    if (i < PN0) {
        const int e = i * 4;
        const int pe_e = (e >= Tq * Hq) ? e - Tq * Hq : e;
        float4 a = *(const float4*)(tok + e);
        float4 p = *(const float4*)(pe + pe_e);
        a.x += p.x; a.y += p.y; a.z += p.z; a.w += p.w;
        union { bf16 b[4]; uint2 u; } H, L;
        H.b[0] = __float2bfloat16(a.x); L.b[0] = __float2bfloat16(a.x - __bfloat162float(H.b[0]));
        H.b[1] = __float2bfloat16(a.y); L.b[1] = __float2bfloat16(a.y - __bfloat162float(H.b[1]));
        H.b[2] = __float2bfloat16(a.z); L.b[2] = __float2bfloat16(a.z - __bfloat162float(H.b[2]));
        H.b[3] = __float2bfloat16(a.w); L.b[3] = __float2bfloat16(a.w - __bfloat162float(H.b[3]));
        ((uint2*)g_tokpe_h)[i] = H.u;
        ((uint2*)g_tokpe_l)[i] = L.u;
    } else if (i < PN1) {
        const int j = i - PN0;
        float4 v = ((const float4*)(in_proj_w + (size_t)Hq * Hq))[j];
        union { bf16 b[4]; uint2 u; } H, L;
        H.b[0] = __float2bfloat16(v.x); L.b[0] = __float2bfloat16(v.x - __bfloat162float(H.b[0]));
        H.b[1] = __float2bfloat16(v.y); L.b[1] = __float2bfloat16(v.y - __bfloat162float(H.b[1]));
        H.b[2] = __float2bfloat16(v.z); L.b[2] = __float2bfloat16(v.z - __bfloat162float(H.b[2]));
        H.b[3] = __float2bfloat16(v.w); L.b[3] = __float2bfloat16(v.w - __bfloat162float(H.b[3]));
        ((uint2*)g_wkv_h)[j] = H.u;
        ((uint2*)g_wkv_l)[j] = L.u;
    } else {
        const float* src;
        __half* dst;
        int j;
        if (i < PN2)      { j = i - PN1; src = out_proj_w; dst = g_wout_f16; }
        else if (i < PN3) { j = i - PN2; src = ffn_w1;     dst = g_w1_f16; }
        else              { j = i - PN3; src = ffn_w2;     dst = g_w2_f16; }
        float4 v = ((const float4*)src)[j];
        __half2 a = __floats2half2_rn(v.x, v.y);
        __half2 b = __floats2half2_rn(v.z, v.w);
        uint2 u; u.x = *(uint32_t*)&a; u.y = *(uint32_t*)&b;
        ((uint2*)dst)[j] = u;
    }
}

// -------------------- mma.sync GEMM (512 threads, 16 warps in 4x4) --------------------
// TERMS=3: bf16 hi/lo split (3 MMAs/kstep).  TERMS=1: fp16 single (1 MMA/kstep).
// MT: m16 tiles per warp (2 -> CTA 128 rows, 1 -> CTA 64 rows). CTA N = 128.
// Warp grid: wm = wid>>2 (0..3), wn = wid&3 (0..3); warp tile (MT*16) x 32.
// EPI: 0 = +bias ; 1 = +bias+resvec ; 2 = relu(+bias) -> fp16 ;
//      3 = +bias+resmat ; 4 = +bias -> fp32, and for n>=Hq also fp16 V copy
#define NSTAGE 3

template<int EPI, int TERMS, int MT>
__global__ __launch_bounds__(512, 1)
void mma_gemm_k(const bf16* __restrict__ Ah, const bf16* __restrict__ Al,
                const bf16* __restrict__ Bh, const bf16* __restrict__ Bl,
                const float* __restrict__ bias, const float* __restrict__ resvec,
                const float* __restrict__ resmat,
                float* __restrict__ C, __half* __restrict__ Ch,
                int M, int N, int K) {
    constexpr int MROWS = 4 * MT * 16;                     // CTA rows
    constexpr uint32_t A_BYTES = (uint32_t)MROWS * 128u;
    constexpr uint32_t BOFF = (TERMS == 3 ? 2u : 1u) * A_BYTES;
    constexpr uint32_t STB = BOFF + (TERMS == 3 ? 2u : 1u) * 16384u;
    constexpr int NQ = (int)(STB / (16u * 512u));
    constexpr int ROWS_A2 = 2 * MROWS;
    extern __shared__ char sm[];
    const uint32_t sb = smem_u32(sm);
    const int tid = threadIdx.x;
    const int wid = tid >> 5, lane = tid & 31;
    const int wm = wid >> 2;            // 0..3
    const int wn = wid & 3;             // 0..3
    const int bm = blockIdx.y * MROWS, bn = blockIdx.x * 128;

    float acc[MT][4][4];
    #pragma unroll
    for (int i = 0; i < MT; i++)
        #pragma unroll
        for (int j = 0; j < 4; j++)
            #pragma unroll
            for (int r = 0; r < 4; r++) acc[i][j][r] = 0.f;

    const int rA_off = (lane & 15);
    const int cqA = lane >> 4;
    const int rB_off = ((lane >> 4) << 3) + (lane & 7);
    const int cqB = (lane >> 3) & 1;

    const int NCH = K >> 6;

    auto issue_part = [&](int c, int part) {
        const int k0 = c << 6;
        const uint32_t sbase = sb + (uint32_t)(c % NSTAGE) * STB;
        #pragma unroll
        for (int q = 0; q < NQ; q++) {
            if ((q & 3) != part) continue;
            const int idx = tid + (q << 9);
            const int rg = idx >> 3, j = idx & 7;
            const bf16* src;
            if (TERMS == 3) {
                if (rg < MROWS)            src = Ah + (size_t)(bm + rg) * K + k0 + j * 8;
                else if (rg < ROWS_A2)     src = Al + (size_t)(bm + rg - MROWS) * K + k0 + j * 8;
                else if (rg < ROWS_A2+128) src = Bh + (size_t)(bn + rg - ROWS_A2) * K + k0 + j * 8;
                else                       src = Bl + (size_t)(bn + rg - ROWS_A2 - 128) * K + k0 + j * 8;
            } else {
                src = (rg < MROWS) ? Ah + (size_t)(bm + rg) * K + k0 + j * 8
                                   : Bh + (size_t)(bn + rg - MROWS) * K + k0 + j * 8;
            }
            cp16(sbase + SW128((uint32_t)idx << 4), src);
        }
    };
    auto issue_chunk = [&](int c) {
        issue_part(c, 0); issue_part(c, 1); issue_part(c, 2); issue_part(c, 3);
        CP_COMMIT();
    };

    issue_chunk(0);
    issue_chunk(1);

    for (int c = 0; c < NCH; c++) {
        cp_wait<1>();
        __syncthreads();
        const uint32_t stage = sb + (uint32_t)(c % NSTAGE) * STB;
        const bool more = (c + 2 < NCH);

        #pragma unroll
        for (int ks = 0; ks < 4; ks++) {
            const int k2 = ks * 2;
            uint32_t ah[MT][4], al[MT][4];
            #pragma unroll
            for (int mt = 0; mt < MT; mt++) {
                const int row = wm * (MT * 16) + mt * 16 + rA_off;
                const uint32_t ph = (uint32_t)((k2 + cqA) ^ (row & 7));
                const uint32_t base = stage + (uint32_t)(row << 7) + (ph << 4);
                ldm_x4(ah[mt][0], ah[mt][1], ah[mt][2], ah[mt][3], base);
                if (TERMS == 3)
                    ldm_x4(al[mt][0], al[mt][1], al[mt][2], al[mt][3], base + A_BYTES);
            }
            uint32_t bh[4][2], bl[4][2];
            #pragma unroll
            for (int p = 0; p < 2; p++) {
                const int row = wn * 32 + p * 16 + rB_off;
                const uint32_t ph = (uint32_t)((k2 + cqB) ^ (row & 7));
                const uint32_t base = stage + BOFF + (uint32_t)(row << 7) + (ph << 4);
                ldm_x4(bh[p*2][0], bh[p*2][1], bh[p*2+1][0], bh[p*2+1][1], base);
                if (TERMS == 3)
                    ldm_x4(bl[p*2][0], bl[p*2][1], bl[p*2+1][0], bl[p*2+1][1], base + 16384u);
            }
            if (more) issue_part(c + 2, ks);
            #pragma unroll
            for (int mt = 0; mt < MT; mt++)
                #pragma unroll
                for (int nt = 0; nt < 4; nt++) {
                    if (TERMS == 3) {
                        mma16816(acc[mt][nt], ah[mt], bh[nt]);
                        mma16816(acc[mt][nt], ah[mt], bl[nt]);
                        mma16816(acc[mt][nt], al[mt], bh[nt]);
                    } else {
                        mma16816h(acc[mt][nt], ah[mt], bh[nt]);
                    }
                }
        }
        if (more) CP_COMMIT();
    }

    // epilogue
    const int gq = lane >> 2, tq = lane & 3;
    #pragma unroll
    for (int mt = 0; mt < MT; mt++) {
        #pragma unroll
        for (int nt = 0; nt < 4; nt++) {
            const int n0 = bn + wn * 32 + nt * 8 + tq * 2;
            const float2 bz = *(const float2*)&bias[n0];
            #pragma unroll
            for (int hrow = 0; hrow < 2; hrow++) {
                const int m = bm + wm * (MT * 16) + mt * 16 + gq + hrow * 8;
                float vx = acc[mt][nt][hrow * 2 + 0] + bz.x;
                float vy = acc[mt][nt][hrow * 2 + 1] + bz.y;
                if (EPI == 1) {
                    const float2 rv = *(const float2*)&resvec[n0];
                    vx += rv.x; vy += rv.y;
                }
                if (EPI == 3) {
                    const float2 rm = *(const float2*)&resmat[(size_t)m * N + n0];
                    vx += rm.x; vy += rm.y;
                }
                if (EPI == 2) {
                    vx = fmaxf(vx, 0.f); vy = fmaxf(vy, 0.f);
                    __half2 hv = __floats2half2_rn(vx, vy);
                    *(uint32_t*)&Ch[(size_t)m * N + n0] = *(uint32_t*)&hv;
                } else {
                    float2 o; o.x = vx; o.y = vy;
                    *(float2*)&C[(size_t)m * N + n0] = o;
                    if (EPI == 4 && n0 >= Hq) {
                        __half2 hv = __floats2half2_rn(vx, vy);
                        *(uint32_t*)&Ch[(size_t)m * Hq + (n0 - Hq)] = *(uint32_t*)&hv;
                    }
                }
            }
        }
    }
}

// -------------------- span attention (fp16 V; scores precomputed; ctx fp16) ------
__global__ __launch_bounds__(256)
void attn_k(const int* __restrict__ span_ids) {
    const int sp = blockIdx.x;
    const int b = sp >> 11;
    const int tid = threadIdx.x;
    __shared__ float sc[NHq][Lq];

    if (!g_mask[sp]) {
        for (int i = tid; i < Hq; i += 256)
            g_ctx_f16[(size_t)sp * Hq + i] = __float2half_rn(0.f);
        return;
    }
    const int start = span_ids[sp * 2 + 0];
    int len = span_ids[sp * 2 + 1] - start;
    if (len > Lq) len = Lq;
    if (len < 1) len = 1;
    const int tok0 = b * Tq + start;

    for (int idx = tid; idx < NHq * Lq; idx += 256) {
        const int n = idx >> 5, l = idx & 31;
        sc[n][l] = (l < len) ? g_tokscore[(tok0 + l) * NHq + n] : -1e30f;
    }
    __syncthreads();

    if (tid < NHq) {
        float mx = -1e30f;
        for (int l = 0; l < len; l++) mx = fmaxf(mx, sc[tid][l]);
        float sum = 0.f;
        for (int l = 0; l < Lq; l++) {
            float e = (l < len) ? __expf(sc[tid][l] - mx) : 0.f;
            sc[tid][l] = e; sum += e;
        }
        float inv = 1.f / sum;
        for (int l = 0; l < Lq; l++) sc[tid][l] *= inv;
    }
    __syncthreads();

    const __half* vb = g_V16 + (size_t)tok0 * Hq;
    for (int d = tid; d < Hq; d += 256) {
        const int n = d >> 6;
        float a = 0.f;
        for (int l = 0; l < len; l++)
            a = fmaf(sc[n][l], __half2float(vb[(size_t)l * Hq + d]), a);
        g_ctx_f16[(size_t)sp * Hq + d] = __float2half_rn(a);
    }
}

// -------------------- LayerNorm --------------------
// MODE 0: Y fp32 + Y16 fp16 (x1)     MODE 1: Y fp32 * mask (final)
template<int MODE>
__global__ __launch_bounds__(256)
void ln_k(const float* __restrict__ X, const float* __restrict__ g,
          const float* __restrict__ bt, float* __restrict__ Y,
          __half* __restrict__ Y16) {
    const int row = blockIdx.x;
    const int tid = threadIdx.x;
    const float* x = X + (size_t)row * Hq;
    __shared__ float red[8];
    __shared__ float sval;

    float v0 = x[tid], v1 = x[tid + 256], v2 = x[tid + 512];
    float s = v0 + v1 + v2;
    #pragma unroll
    for (int o = 16; o > 0; o >>= 1) s += __shfl_down_sync(0xffffffffu, s, o);
    if ((tid & 31) == 0) red[tid >> 5] = s;
    __syncthreads();
    if (tid == 0) {
        float t = 0.f;
        #pragma unroll
        for (int w = 0; w < 8; w++) t += red[w];
        sval = t * (1.f / Hq);
    }
    __syncthreads();
    const float mean = sval;
    const float d0 = v0 - mean, d1 = v1 - mean, d2 = v2 - mean;
    float vs = d0 * d0 + d1 * d1 + d2 * d2;
    __syncthreads();
    #pragma unroll
    for (int o = 16; o > 0; o >>= 1) vs += __shfl_down_sync(0xffffffffu, vs, o);
    if ((tid & 31) == 0) red[tid >> 5] = vs;
    __syncthreads();
    if (tid == 0) {
        float t = 0.f;
        #pragma unroll
        for (int w = 0; w < 8; w++) t += red[w];
        sval = rsqrtf(t * (1.f / Hq) + 1e-5f);
    }
    __syncthreads();
    const float rstd = sval;
    float m = 1.f;
    if (MODE == 1) m = g_mask[row] ? 1.f : 0.f;
    float* y = Y + (size_t)row * Hq;
    float r0 = (d0 * rstd * g[tid]       + bt[tid])       * m;
    float r1 = (d1 * rstd * g[tid + 256] + bt[tid + 256]) * m;
    float r2 = (d2 * rstd * g[tid + 512] + bt[tid + 512]) * m;
    y[tid] = r0; y[tid + 256] = r1; y[tid + 512] = r2;
    if (MODE == 0) {
        Y16[(size_t)row * Hq + tid]       = __float2half_rn(r0);
        Y16[(size_t)row * Hq + tid + 256] = __float2half_rn(r1);
        Y16[(size_t)row * Hq + tid + 512] = __float2half_rn(r2);
    }
}

// -------------------- launch --------------------
extern "C" void kernel_launch(void* const* d_in, const int* in_sizes, int n_in,
                              void* d_out, int out_size) {
    const float* token_reps = (const float*)d_in[0];
    const int* span_ids     = (const int*)d_in[1];
    const void* span_masks  = (const void*)d_in[2];
    int k = 3;
    if (n_in >= 16 && in_sizes[3] == 1) k = 4;
    const float* pe          = (const float*)d_in[k + 0];
    const float* dummy_query = (const float*)d_in[k + 1];
    const float* in_proj_w   = (const float*)d_in[k + 2];
    const float* in_proj_b   = (const float*)d_in[k + 3];
    const float* out_proj_w  = (const float*)d_in[k + 4];
    const float* out_proj_b  = (const float*)d_in[k + 5];
    const float* norm_g      = (const float*)d_in[k + 6];
    const float* norm_b      = (const float*)d_in[k + 7];
    const float* ffn_w1      = (const float*)d_in[k + 8];
    const float* ffn_b1      = (const float*)d_in[k + 9];
    const float* ffn_w2      = (const float*)d_in[k + 10];
    const float* ffn_b2      = (const float*)d_in[k + 11];

    float *p_KV, *p_pre1, *p_x1, *p_pre2;
    bf16 *p_tokpe_h, *p_tokpe_l, *p_wkv_h, *p_wkv_l;
    __half *p_wout, *p_w1, *p_w2, *p_ctx16, *p_x1_16, *p_h1_16, *p_V16;
    cudaGetSymbolAddress((void**)&p_KV, g_KV);
    cudaGetSymbolAddress((void**)&p_V16, g_V16);
    cudaGetSymbolAddress((void**)&p_pre1, g_pre1);
    cudaGetSymbolAddress((void**)&p_x1, g_x1);
    cudaGetSymbolAddress((void**)&p_pre2, g_pre2);
    cudaGetSymbolAddress((void**)&p_tokpe_h, g_tokpe_h);
    cudaGetSymbolAddress((void**)&p_tokpe_l, g_tokpe_l);
    cudaGetSymbolAddress((void**)&p_wkv_h, g_wkv_h);
    cudaGetSymbolAddress((void**)&p_wkv_l, g_wkv_l);
    cudaGetSymbolAddress((void**)&p_wout, g_wout_f16);
    cudaGetSymbolAddress((void**)&p_w1, g_w1_f16);
    cudaGetSymbolAddress((void**)&p_w2, g_w2_f16);
    cudaGetSymbolAddress((void**)&p_ctx16, g_ctx_f16);
    cudaGetSymbolAddress((void**)&p_x1_16, g_x1_f16);
    cudaGetSymbolAddress((void**)&p_h1_16, g_h1_f16);

    // stage bytes: T3 MT1 = 48KB, T1 MT2 = 32KB, T1 MT1 = 24KB; x3 stages
    const int SM_T3M1 = 49152 * NSTAGE;   // 147456
    const int SM_T1M2 = 32768 * NSTAGE;   // 98304
    const int SM_T1M1 = 24576 * NSTAGE;   // 73728
    cudaFuncSetAttribute(mma_gemm_k<4, 3, 1>, cudaFuncAttributeMaxDynamicSharedMemorySize, SM_T3M1);
    cudaFuncSetAttribute(mma_gemm_k<1, 1, 1>, cudaFuncAttributeMaxDynamicSharedMemorySize, SM_T1M1);
    cudaFuncSetAttribute(mma_gemm_k<2, 1, 2>, cudaFuncAttributeMaxDynamicSharedMemorySize, SM_T1M2);
    cudaFuncSetAttribute(mma_gemm_k<3, 1, 1>, cudaFuncAttributeMaxDynamicSharedMemorySize, SM_T1M1);

    // 0. canonicalize mask; project q; fused operand prep
    mask_conv_k<<<1, 256>>>(span_masks);
    compute_q_k<<<3, 256>>>(dummy_query, in_proj_w, in_proj_b);
    prep_k<<<(PN4 + 255) / 256, 256>>>(token_reps, pe, in_proj_w, out_proj_w, ffn_w1, ffn_w2);

    // 2. KV = (tok+pe) @ Wkv^T + bkv  (1024 x 1536 x 768) bf16x3, CTA 64x128; emits fp16 V
    mma_gemm_k<4, 3, 1><<<dim3(12, 16), 512, SM_T3M1>>>(
        p_tokpe_h, p_tokpe_l, p_wkv_h, p_wkv_l,
        in_proj_b + Hq, nullptr, nullptr, p_KV, p_V16,
        NTOK, 2 * Hq, Hq);

    // 3. per-token scores, then per-span attention -> ctx fp16
    score_k<<<NTOK / 8, 256>>>();
    attn_k<<<NSPAN, 256>>>(span_ids);

    // 4. pre1 = ctx @ Wout^T + bout + dummy_query   (4096 x 768 x 768) fp16, CTA 64x128
    mma_gemm_k<1, 1, 1><<<dim3(6, 64), 512, SM_T1M1>>>(
        (const bf16*)p_ctx16, nullptr, (const bf16*)p_wout, nullptr,
        out_proj_b, dummy_query, nullptr, p_pre1, nullptr,
        NSPAN, Hq, Hq);

    // 5. x1 = LN(pre1)  (+ fp16)
    ln_k<0><<<NSPAN, 256>>>(p_pre1, norm_g, norm_b, p_x1, p_x1_16);

    // 6. h1 = relu(x1 @ W1^T + b1)   (4096 x 3072 x 768) fp16, CTA 128x128
    mma_gemm_k<2, 1, 2><<<dim3(24, 32), 512, SM_T1M2>>>(
        (const bf16*)p_x1_16, nullptr, (const bf16*)p_w1, nullptr,
        ffn_b1, nullptr, nullptr, nullptr, p_h1_16,
        NSPAN, IM, Hq);

    // 7. pre2 = h1 @ W2^T + b2 + x1   (4096 x 768 x 3072) fp16, CTA 64x128
    mma_gemm_k<3, 1, 1><<<dim3(6, 64), 512, SM_T1M1>>>(
        (const bf16*)p_h1_16, nullptr, (const bf16*)p_w2, nullptr,
        ffn_b2, nullptr, p_x1, p_pre2, nullptr,
        NSPAN, Hq, IM);

    // 8. out = LN(pre2) * mask
    ln_k<1><<<NSPAN, 256>>>(p_pre2, norm_g, norm_b, (float*)d_out, nullptr);
}